// round 1
// baseline (speedup 1.0000x reference)
#include <cuda_runtime.h>

// 3x3 conv, stride 1, pad 1, single channel, X: (32, 1024, 1024) fp32.
// Register-blocked: each thread computes a 4x4 output tile using float4 I/O.
// Block = 256 threads covers one full 1024-wide row band of 4 rows.
// Grid = 32 batches * 256 row-groups = 8192 blocks.

#define IMG_W 1024
#define IMG_H 1024

__global__ __launch_bounds__(256) void conv3x3_kernel(
    const float* __restrict__ X,
    const float* __restrict__ Wt,
    float* __restrict__ Y)
{
    const int tid   = threadIdx.x;
    const int bx    = blockIdx.x;
    const int batch = bx >> 8;        // / 256 row-groups
    const int rg    = bx & 255;
    const int r0    = rg << 2;        // first output row of this thread's tile
    const int c0    = tid << 2;       // first output col (float4 aligned)

    const size_t plane = (size_t)IMG_W * IMG_H;
    const float* Xb = X + (size_t)batch * plane;
    float*       Yb = Y + (size_t)batch * plane;

    // Load the 3x3 weights (uniform across threads -> broadcast, L1/L2 cached)
    float w[9];
#pragma unroll
    for (int i = 0; i < 9; i++) w[i] = __ldg(Wt + i);

    float acc[4][4];
#pragma unroll
    for (int i = 0; i < 4; i++)
#pragma unroll
        for (int j = 0; j < 4; j++) acc[i][j] = 0.0f;

    // Stream 6 input rows (r0-1 .. r0+4); each contributes to up to 3 output rows.
#pragma unroll
    for (int rr = -1; rr <= 4; rr++) {
        const int r = r0 + rr;
        float row[6];
        if (r >= 0 && r < IMG_H) {
            const float* p = Xb + (size_t)r * IMG_W + c0;
            const float4 v = *reinterpret_cast<const float4*>(p);
            row[1] = v.x; row[2] = v.y; row[3] = v.z; row[4] = v.w;
            row[0] = (c0 > 0)           ? __ldg(p - 1) : 0.0f;
            row[5] = (c0 + 4 < IMG_W)   ? __ldg(p + 4) : 0.0f;
        } else {
#pragma unroll
            for (int j = 0; j < 6; j++) row[j] = 0.0f;
        }

        // Output row i (local 0..3) uses input rows r0+i-1 .. r0+i+1.
        // Kernel row for this input row: ky = rr - i + 1 (must be in [0,2]).
#pragma unroll
        for (int i = 0; i < 4; i++) {
            const int ky = rr - i + 1;
            if (ky >= 0 && ky <= 2) {          // compile-time after unroll
#pragma unroll
                for (int j = 0; j < 4; j++) {
                    acc[i][j] = fmaf(w[ky * 3 + 0], row[j],
                                fmaf(w[ky * 3 + 1], row[j + 1],
                                fmaf(w[ky * 3 + 2], row[j + 2], acc[i][j])));
                }
            }
        }
    }

#pragma unroll
    for (int i = 0; i < 4; i++) {
        float4 o;
        o.x = acc[i][0]; o.y = acc[i][1]; o.z = acc[i][2]; o.w = acc[i][3];
        *reinterpret_cast<float4*>(Yb + (size_t)(r0 + i) * IMG_W + c0) = o;
    }
}

extern "C" void kernel_launch(void* const* d_in, const int* in_sizes, int n_in,
                              void* d_out, int out_size)
{
    const float* X  = (const float*)d_in[0];   // (32, 1024, 1024) fp32
    const float* Wt = (const float*)d_in[1];   // (3, 3) fp32
    float* Y        = (float*)d_out;           // (32, 1024, 1024) fp32

    // 256 threads * 4 cols = 1024 cols; 4 rows per block; 256 row-groups; 32 batches
    const int grid = 32 * 256;
    conv3x3_kernel<<<grid, 256>>>(X, Wt, Y);
}